// round 16
// baseline (speedup 1.0000x reference)
#include <cuda_runtime.h>
#include <math_constants.h>

#define B_    32
#define N_    128
#define C_    25
#define NC    3200                      // N_*C_ candidates per center
#define S_    13107200                  // B_*N_*N_*C_ elements per output tensor
#define RAD2  64.0f
#define EPS2  1e-4f
#define NT    256
#define NBIN  256
#define CAP   192
#define PREF  4.0f                      // candidate-list bound (rank-32 d2 ~ 2.4; E[np]~67)

#define PBLK  1184                      // 148 SMs * 8 blocks = one full wave
#define ITERS 4
#define SLOTS (PBLK * ITERS)            // 4736 tickets per launch (replay-exact)
#define WREAL (B_ * N_)                 // 4096 real centers

__device__ unsigned g_ctr;              // monotone ticket counter (never reset)

__global__ __launch_bounds__(NT, 8)
void pbc_graph_kernel(const float* __restrict__ pos,
                      const float* __restrict__ cell,
                      float* __restrict__ out) {
    const int tid = threadIdx.x;

    __shared__ float4 spos4[N_];
    __shared__ float4 soff[C_];
    __shared__ float  sctf[C_];
    __shared__ unsigned long long plist[CAP];
    __shared__ int    hist[NBIN];               // fallback only
    __shared__ int    s_pn, s_n, s_t, s_cntlo, s_total, s_slot;
    __shared__ unsigned long long s_Tkey;
    __shared__ float  s_Tf;
    __shared__ int    s_Tc;

    // b-independent LUT, once per block
    if (tid < C_) sctf[tid] = (float)(5 * (tid / 5 + tid % 5));

    for (int it = 0; it < ITERS; it++) {
        // ---- grab ticket (dynamic balancing; exactly SLOTS grabs/launch) ----
        if (tid == 0) {
            unsigned old = atomicAdd(&g_ctr, 1u);
            s_slot = (int)(old % SLOTS);
            s_pn = 0; s_n = 0; s_t = -1; s_cntlo = 0;
        }
        __syncthreads();                        // slot barrier (also orders
                                                // prev-iter shared reads vs below)
        const int center = s_slot;
        if (center >= WREAL) continue;          // uniform across block
        const int b = center >> 7;
        const int i = center & 127;

        // ---- zero-fill all three output streams first (drains behind logic) ----
        {
            const float4 z4 = make_float4(0.f, 0.f, 0.f, 0.f);
            float4* o0 = (float4*)out                    + ((size_t)center * NC >> 2);
            float4* o1 = (float4*)(out + (size_t)S_)     + ((size_t)center * NC >> 2);
            float4* o2 = (float4*)(out + (size_t)2 * S_) + ((size_t)center * NC >> 2);
#pragma unroll
            for (int k = 0; k < 3; k++) {
                int v = tid + 256 * k;
                o0[v] = z4; o1[v] = z4; o2[v] = z4;
            }
            if (tid < 32) {
                int v = 768 + tid;
                o0[v] = z4; o1[v] = z4; o2[v] = z4;
            }
        }

        // per-image count baseline (fallback corrections handled below)
        if (i == 0 && tid == 0)
            out[(size_t)3 * S_ + b] = (float)(N_ * 32);

        // ---- shared setup for this center's image ----
        if (tid < N_) {
            const float* p = pos + (size_t)b * N_ * 3 + tid * 3;
            spos4[tid] = make_float4(p[0], p[1], p[2], 0.0f);
        }
        if (tid >= N_ && tid < N_ + C_) {
            int c = tid - N_;
            float u0 = (float)(c / 5 - 2);
            float u1 = (float)(c % 5 - 2);
            const float* cb = cell + b * 9;
            soff[c] = make_float4(
                __fmaf_rn(u0, cb[0], __fmul_rn(u1, cb[3])),
                __fmaf_rn(u0, cb[1], __fmul_rn(u1, cb[4])),
                __fmaf_rn(u0, cb[2], __fmul_rn(u1, cb[5])), 0.0f);
        }
        __syncthreads();                        // setup barrier

        const float4 pi = spos4[i];

        // ---- phase 1: d2 per (j,half); push d2<PREF keys into shared list ----
        const int j    = tid >> 1;
        const int half = tid & 1;
        const int cbeg = half ? 13 : 0;
        const int cend = half ? 25 : 13;
        const int jbase = j * 25;
        const float4 rj = spos4[j];
        const float rx = __fsub_rn(rj.x, pi.x);
        const float ry = __fsub_rn(rj.y, pi.y);
        const float rz = __fsub_rn(rj.z, pi.z);
        for (int c = cbeg; c < cend; c++) {
            float4 o = soff[c];
            float dx = __fadd_rn(rx, o.x);
            float dy = __fadd_rn(ry, o.y);
            float dz = __fadd_rn(rz, o.z);
            float d2 = __fmaf_rn(dx, dx, __fmaf_rn(dy, dy, __fmul_rn(dz, dz)));
            if (d2 < PREF && d2 > EPS2) {
                int p = atomicAdd(&s_pn, 1);
                if (p < CAP)
                    plist[p] = ((unsigned long long)__float_as_uint(d2) << 12)
                             | (unsigned)(jbase + c);
            }
        }
        __syncthreads();                        // phase-1 barrier

        const int  np     = s_pn;
        const bool common = (np >= 32 && np <= CAP);

        if (common) {
            // ---- selection: direct rank; threshold = 32nd smallest key ----
            if (tid < np) {
                unsigned long long k = plist[tid];
                int r = 0;
                for (int m = 0; m < np; m++) r += (plist[m] < k) ? 1 : 0;
                if (r == 31) s_Tkey = k;
            }
            __syncthreads();                    // rank barrier (orders zeros too)

            // ---- fixup: write the exactly-32 kept entries ----
            const unsigned long long T = s_Tkey;
            if (tid < np) {
                unsigned long long k = plist[tid];
                if (k <= T) {
                    float d2  = __uint_as_float((unsigned)(k >> 12));
                    int  cand = (int)(k & 0xFFFu);
                    const size_t base = (size_t)center * NC + cand;
                    out[base]                  = sqrtf(d2);
                    out[(size_t)S_ + base]     = sctf[cand % 25];
                    out[(size_t)2 * S_ + base] = 1.0f;
                }
            }
        } else {
            // ---- fallback (rare): coarse-hist path with recompute ----
            if (tid < NBIN) hist[tid] = 0;
            __syncthreads();
            for (int c = cbeg; c < cend; c++) {
                float4 o = soff[c];
                float dx = __fadd_rn(rx, o.x);
                float dy = __fadd_rn(ry, o.y);
                float dz = __fadd_rn(rz, o.z);
                float d2 = __fmaf_rn(dx, dx, __fmaf_rn(dy, dy, __fmul_rn(dz, dz)));
                if (d2 <= RAD2 && d2 > EPS2)
                    atomicAdd(&hist[min((int)(d2 * 4.0f), NBIN - 1)], 1);
            }
            __syncthreads();
            if (tid < 32) {
                int loc[8], sum = 0;
#pragma unroll
                for (int k = 0; k < 8; k++) { loc[k] = hist[tid * 8 + k]; sum += loc[k]; }
                int pre = sum;
#pragma unroll
                for (int d = 1; d < 32; d <<= 1) {
                    int v = __shfl_up_sync(0xffffffffu, pre, d);
                    if (tid >= d) pre += v;
                }
                int total = __shfl_sync(0xffffffffu, pre, 31);
                pre -= sum;
                if (tid == 0) s_total = total;
                if (total > 32 && pre < 32 && 32 <= pre + sum) {
                    int cum = pre;
#pragma unroll
                    for (int k = 0; k < 8; k++) {
                        if (cum < 32 && cum + loc[k] >= 32) { s_t = tid * 8 + k; s_cntlo = cum; }
                        cum += loc[k];
                    }
                }
            }
            __syncthreads();
            if (s_total > 32) {
                const int tbin = s_t;
                for (int c = cbeg; c < cend; c++) {
                    float4 o = soff[c];
                    float dx = __fadd_rn(rx, o.x);
                    float dy = __fadd_rn(ry, o.y);
                    float dz = __fadd_rn(rz, o.z);
                    float d2 = __fmaf_rn(dx, dx, __fmaf_rn(dy, dy, __fmul_rn(dz, dz)));
                    if (d2 <= RAD2 && d2 > EPS2 &&
                        min((int)(d2 * 4.0f), NBIN - 1) == tbin) {
                        int p = atomicAdd(&s_n, 1);
                        if (p < CAP)
                            plist[p] = ((unsigned long long)__float_as_uint(d2) << 12)
                                     | (unsigned)(jbase + c);
                    }
                }
                __syncthreads();
                int n = min(s_n, CAP);
                int need = 32 - s_cntlo;
                if (tid < n) {
                    unsigned long long k = plist[tid];
                    int r = 0;
                    for (int m = 0; m < n; m++) r += (plist[m] < k) ? 1 : 0;
                    if (r == need - 1) {
                        s_Tf = __uint_as_float((unsigned)(k >> 12));
                        s_Tc = (int)(k & 0xFFFu);
                    }
                }
                __syncthreads();
            } else {
                if (tid == 0) { s_Tf = CUDART_INF_F; s_Tc = 0x7FFFFFFF; }
                __syncthreads();
            }
            // fixup by recompute (ordered after zeros by the barriers above)
            const float Tf = s_Tf;
            const int   Tc = s_Tc;
            for (int c = cbeg; c < cend; c++) {
                float4 o = soff[c];
                float dx = __fadd_rn(rx, o.x);
                float dy = __fadd_rn(ry, o.y);
                float dz = __fadd_rn(rz, o.z);
                float d2 = __fmaf_rn(dx, dx, __fmaf_rn(dy, dy, __fmul_rn(dz, dz)));
                bool within = (d2 <= RAD2) && (d2 > EPS2);
                int  cand = jbase + c;
                if (within && (d2 < Tf || (d2 == Tf && cand <= Tc))) {
                    const size_t base = (size_t)center * NC + cand;
                    out[base]                  = sqrtf(d2);
                    out[(size_t)S_ + base]     = sctf[c];
                    out[(size_t)2 * S_ + base] = 1.0f;
                }
            }
            // exact count correction (nonzero only if <32 atoms within 8A)
            if (tid == 0) {
                int delta = min(s_total, 32) - 32;
                if (delta != 0)
                    atomicAdd(&out[(size_t)3 * S_ + b], (float)delta);
            }
        }
    }
}

extern "C" void kernel_launch(void* const* d_in, const int* in_sizes, int n_in,
                              void* d_out, int out_size) {
    const float* pos;
    const float* cell;
    if (n_in >= 2 && in_sizes[0] == B_ * N_ * 3) {
        pos  = (const float*)d_in[0];
        cell = (const float*)d_in[1];
    } else {
        pos  = (const float*)d_in[1];
        cell = (const float*)d_in[0];
    }
    float* out = (float*)d_out;

    pbc_graph_kernel<<<PBLK, NT>>>(pos, cell, out);
}

// round 17
// speedup vs baseline: 1.2141x; 1.2141x over previous
#include <cuda_runtime.h>
#include <math_constants.h>

#define B_    32
#define N_    128
#define C_    25
#define NC    3200                      // N_*C_ candidates per center
#define S_    13107200                  // B_*N_*N_*C_ elements per output tensor
#define RAD2  64.0f
#define EPS2  1e-4f
#define NT    256
#define NBIN  256
#define CAP   192
#define PREF  4.0f                      // candidate-list bound (rank-32 d2 ~ 2.4; E[np]~67)

__global__ __launch_bounds__(NT, 8)
void pbc_graph_kernel(const float* __restrict__ pos,
                      const float* __restrict__ cell,
                      float* __restrict__ out) {
    const int center = blockIdx.x;      // b*128 + i
    const int b = center >> 7;
    const int i = center & 127;
    const int tid = threadIdx.x;

    __shared__ float4 spos4[N_];
    __shared__ float4 soff[C_];
    __shared__ float  sctf[C_];
    __shared__ unsigned long long plist[CAP];   // keys (d2bits<<12 | cand), d2<PREF
    __shared__ int    hist[NBIN];               // fallback only
    __shared__ int    s_pn, s_n, s_t, s_cntlo, s_total;
    __shared__ unsigned long long s_Tkey;
    __shared__ float  s_Tf;
    __shared__ int    s_Tc;

    const float4 z4 = make_float4(0.f, 0.f, 0.f, 0.f);
    float4* o0 = (float4*)out                    + ((size_t)center * NC >> 2);
    float4* o1 = (float4*)(out + (size_t)S_)     + ((size_t)center * NC >> 2);
    float4* o2 = (float4*)(out + (size_t)2 * S_) + ((size_t)center * NC >> 2);

    // ---- issue setup loads early (latency-bound) ----
    float p0 = 0.f, p1 = 0.f, p2 = 0.f;
    if (tid < N_) {
        const float* p = pos + (size_t)b * N_ * 3 + tid * 3;
        p0 = __ldg(p); p1 = __ldg(p + 1); p2 = __ldg(p + 2);
    }

    // per-image count baseline (fallback corrections are ~impossible; exact
    // correction below covers them)
    if (i == 0 && tid == 0)
        out[(size_t)3 * S_ + b] = (float)(N_ * 32);

    // ---- zero-fill chunk A (1/3 of stores + the tail groups) ----
    {
        o0[tid] = z4; o1[tid] = z4; o2[tid] = z4;
        if (tid < 32) {
            int v = 768 + tid;
            o0[v] = z4; o1[v] = z4; o2[v] = z4;
        }
    }

    // ---- shared setup ----
    if (tid < N_) spos4[tid] = make_float4(p0, p1, p2, 0.0f);
    if (tid >= N_ && tid < N_ + C_) {
        int c = tid - N_;
        float u0 = (float)(c / 5 - 2);
        float u1 = (float)(c % 5 - 2);
        const float* cb = cell + b * 9;
        soff[c] = make_float4(
            __fmaf_rn(u0, cb[0], __fmul_rn(u1, cb[3])),
            __fmaf_rn(u0, cb[1], __fmul_rn(u1, cb[4])),
            __fmaf_rn(u0, cb[2], __fmul_rn(u1, cb[5])), 0.0f);
        sctf[c] = (float)(5 * (c / 5 + c % 5));
    }
    if (tid == 0) { s_pn = 0; s_n = 0; s_t = -1; s_cntlo = 0; }
    __syncthreads();

    const float4 pi = spos4[i];

    // ---- phase 1: d2 per (j,half); push d2<PREF keys into shared list ----
    const int j    = tid >> 1;
    const int half = tid & 1;
    const int cbeg = half ? 13 : 0;
    const int cend = half ? 25 : 13;
    const int jbase = j * 25;
    const float4 rj = spos4[j];
    const float rx = __fsub_rn(rj.x, pi.x);
    const float ry = __fsub_rn(rj.y, pi.y);
    const float rz = __fsub_rn(rj.z, pi.z);
    for (int c = cbeg; c < cend; c++) {
        float4 o = soff[c];
        float dx = __fadd_rn(rx, o.x);
        float dy = __fadd_rn(ry, o.y);
        float dz = __fadd_rn(rz, o.z);
        float d2 = __fmaf_rn(dx, dx, __fmaf_rn(dy, dy, __fmul_rn(dz, dz)));
        if (d2 < PREF && d2 > EPS2) {
            int p = atomicAdd(&s_pn, 1);
            if (p < CAP)
                plist[p] = ((unsigned long long)__float_as_uint(d2) << 12)
                         | (unsigned)(jbase + c);
        }
    }

    // ---- zero-fill chunk B (overlaps phase-1 store/atomic drain) ----
    {
        int v = tid + 256;
        o0[v] = z4; o1[v] = z4; o2[v] = z4;
    }
    __syncthreads();                    // phase-1 barrier

    const int  np     = s_pn;
    const bool common = (np >= 32 && np <= CAP);

    // ---- zero-fill chunk C (before rank; ordered before fixup by barriers) ----
    {
        int v = tid + 512;
        o0[v] = z4; o1[v] = z4; o2[v] = z4;
    }

    if (common) {
        // ---- selection: direct rank among np keys; threshold = 32nd smallest ----
        if (tid < np) {
            unsigned long long k = plist[tid];
            int r = 0;
            for (int m = 0; m < np; m++) r += (plist[m] < k) ? 1 : 0;
            if (r == 31) s_Tkey = k;
        }
        __syncthreads();                 // rank barrier (orders all zeros too)

        // ---- fixup: write the exactly-32 kept entries ----
        const unsigned long long T = s_Tkey;
        if (tid < np) {
            unsigned long long k = plist[tid];
            if (k <= T) {
                float d2  = __uint_as_float((unsigned)(k >> 12));
                int  cand = (int)(k & 0xFFFu);
                const size_t base = (size_t)center * NC + cand;
                out[base]                  = sqrtf(d2);
                out[(size_t)S_ + base]     = sctf[cand % 25];
                out[(size_t)2 * S_ + base] = 1.0f;
            }
        }
        // count contribution is exactly 32: covered by the baseline write.
    } else {
        // ---- fallback (rare): coarse-hist path with recompute ----
        if (tid < NBIN) hist[tid] = 0;
        __syncthreads();
        for (int c = cbeg; c < cend; c++) {
            float4 o = soff[c];
            float dx = __fadd_rn(rx, o.x);
            float dy = __fadd_rn(ry, o.y);
            float dz = __fadd_rn(rz, o.z);
            float d2 = __fmaf_rn(dx, dx, __fmaf_rn(dy, dy, __fmul_rn(dz, dz)));
            if (d2 <= RAD2 && d2 > EPS2)
                atomicAdd(&hist[min((int)(d2 * 4.0f), NBIN - 1)], 1);
        }
        __syncthreads();
        if (tid < 32) {
            int loc[8], sum = 0;
#pragma unroll
            for (int k = 0; k < 8; k++) { loc[k] = hist[tid * 8 + k]; sum += loc[k]; }
            int pre = sum;
#pragma unroll
            for (int d = 1; d < 32; d <<= 1) {
                int v = __shfl_up_sync(0xffffffffu, pre, d);
                if (tid >= d) pre += v;
            }
            int total = __shfl_sync(0xffffffffu, pre, 31);
            pre -= sum;
            if (tid == 0) s_total = total;
            if (total > 32 && pre < 32 && 32 <= pre + sum) {
                int cum = pre;
#pragma unroll
                for (int k = 0; k < 8; k++) {
                    if (cum < 32 && cum + loc[k] >= 32) { s_t = tid * 8 + k; s_cntlo = cum; }
                    cum += loc[k];
                }
            }
        }
        __syncthreads();
        if (s_total > 32) {
            const int tbin = s_t;
            for (int c = cbeg; c < cend; c++) {
                float4 o = soff[c];
                float dx = __fadd_rn(rx, o.x);
                float dy = __fadd_rn(ry, o.y);
                float dz = __fadd_rn(rz, o.z);
                float d2 = __fmaf_rn(dx, dx, __fmaf_rn(dy, dy, __fmul_rn(dz, dz)));
                if (d2 <= RAD2 && d2 > EPS2 &&
                    min((int)(d2 * 4.0f), NBIN - 1) == tbin) {
                    int p = atomicAdd(&s_n, 1);
                    if (p < CAP)
                        plist[p] = ((unsigned long long)__float_as_uint(d2) << 12)
                                 | (unsigned)(jbase + c);
                }
            }
            __syncthreads();
            int n = min(s_n, CAP);
            int need = 32 - s_cntlo;
            if (tid < n) {
                unsigned long long k = plist[tid];
                int r = 0;
                for (int m = 0; m < n; m++) r += (plist[m] < k) ? 1 : 0;
                if (r == need - 1) {
                    s_Tf = __uint_as_float((unsigned)(k >> 12));
                    s_Tc = (int)(k & 0xFFFu);
                }
            }
            __syncthreads();
        } else {
            if (tid == 0) { s_Tf = CUDART_INF_F; s_Tc = 0x7FFFFFFF; }
            __syncthreads();
        }
        // fixup by recompute (ordered after zero stores by barriers above)
        const float Tf = s_Tf;
        const int   Tc = s_Tc;
        for (int c = cbeg; c < cend; c++) {
            float4 o = soff[c];
            float dx = __fadd_rn(rx, o.x);
            float dy = __fadd_rn(ry, o.y);
            float dz = __fadd_rn(rz, o.z);
            float d2 = __fmaf_rn(dx, dx, __fmaf_rn(dy, dy, __fmul_rn(dz, dz)));
            bool within = (d2 <= RAD2) && (d2 > EPS2);
            int  cand = jbase + c;
            if (within && (d2 < Tf || (d2 == Tf && cand <= Tc))) {
                const size_t base = (size_t)center * NC + cand;
                out[base]                  = sqrtf(d2);
                out[(size_t)S_ + base]     = sctf[c];
                out[(size_t)2 * S_ + base] = 1.0f;
            }
        }
        // exact count correction (nonzero only if <32 atoms within 8A)
        if (tid == 0) {
            int delta = min(s_total, 32) - 32;
            if (delta != 0)
                atomicAdd(&out[(size_t)3 * S_ + b], (float)delta);
        }
    }
}

extern "C" void kernel_launch(void* const* d_in, const int* in_sizes, int n_in,
                              void* d_out, int out_size) {
    const float* pos;
    const float* cell;
    if (n_in >= 2 && in_sizes[0] == B_ * N_ * 3) {
        pos  = (const float*)d_in[0];
        cell = (const float*)d_in[1];
    } else {
        pos  = (const float*)d_in[1];
        cell = (const float*)d_in[0];
    }
    float* out = (float*)d_out;

    pbc_graph_kernel<<<B_ * N_, NT>>>(pos, cell, out);
}